// round 9
// baseline (speedup 1.0000x reference)
#include <cuda_runtime.h>
#include <cuda_bf16.h>
#include <math.h>

// ---------------------------------------------------------------------------
// Scratch buffers (device globals; no allocation allowed)
// ---------------------------------------------------------------------------
#define B 64
#define F 32

__device__ __align__(128) float g_f128[(size_t)B * F * 128 * 128];   // 134 MB
__device__ __align__(128) float g_bufA[(size_t)B * F * 64 * 64];     // 33.5 MB each
__device__ __align__(128) float g_bufB[(size_t)B * F * 64 * 64];
__device__ __align__(128) float g_bufC[(size_t)B * F * 64 * 64];
__device__ __align__(128) float g_bufD[(size_t)B * F * 64 * 64];
__device__ float g_mean[B * F];
__device__ float g_rstd[B * F];

// ---------------------------------------------------------------------------
// Instance-norm statistics: one block per (b,c), reduces HW elements
// ---------------------------------------------------------------------------
__global__ void in_stats_kernel(const float* __restrict__ in, int HW,
                                float* __restrict__ mean, float* __restrict__ rstd)
{
    int bc = blockIdx.x;
    const float4* p = (const float4*)(in + (size_t)bc * HW);
    int n4 = HW >> 2;
    float s1 = 0.f, s2 = 0.f;
    for (int i = threadIdx.x; i < n4; i += blockDim.x) {
        float4 v = p[i];
        s1 += v.x + v.y + v.z + v.w;
        s2 += v.x * v.x + v.y * v.y + v.z * v.z + v.w * v.w;
    }
    __shared__ float sh1[32], sh2[32];
    #pragma unroll
    for (int o = 16; o; o >>= 1) {
        s1 += __shfl_down_sync(0xffffffffu, s1, o);
        s2 += __shfl_down_sync(0xffffffffu, s2, o);
    }
    int lane = threadIdx.x & 31, w = threadIdx.x >> 5;
    if (lane == 0) { sh1[w] = s1; sh2[w] = s2; }
    __syncthreads();
    if (w == 0) {
        int nw = blockDim.x >> 5;
        s1 = lane < nw ? sh1[lane] : 0.f;
        s2 = lane < nw ? sh2[lane] : 0.f;
        #pragma unroll
        for (int o = 16; o; o >>= 1) {
            s1 += __shfl_down_sync(0xffffffffu, s1, o);
            s2 += __shfl_down_sync(0xffffffffu, s2, o);
        }
        if (lane == 0) {
            float m = s1 / (float)HW;
            float var = s2 / (float)HW - m * m;
            mean[bc] = m;
            rstd[bc] = rsqrtf(var + 1e-5f);
        }
    }
}

// ---------------------------------------------------------------------------
// conv1: 7x7 stride 2 pad 3, Cin=3 (IN applied on the fly, NO relu), Cout=32
// Input [64,3,256,256] -> output [64,32,128,128]
// Block: 256 threads, 16x16 output tile, 4px x 8f register tile per thread.
// ---------------------------------------------------------------------------
__global__ void conv1_kernel(const float* __restrict__ x,
                             const float* __restrict__ w,      // [32][3][7][7]
                             const float* __restrict__ bias,   // [32]
                             const float* __restrict__ mean,
                             const float* __restrict__ rstd,
                             float* __restrict__ out)
{
    __shared__ __align__(16) float s_w[147][32];   // [c*49+k][f]  (first: keep 16B base)
    __shared__ __align__(16) float s_in[3][37][38];
    int b = blockIdx.z;
    int oh0 = blockIdx.y * 16, ow0 = blockIdx.x * 16;
    int tid = threadIdx.x;

    for (int i = tid; i < 32 * 147; i += 256) {
        int f = i / 147, ck = i - f * 147;
        s_w[ck][f] = w[i];
    }
    int ih0 = oh0 * 2 - 3, iw0 = ow0 * 2 - 3;
    for (int c = 0; c < 3; c++) {
        int bc = b * 3 + c;
        float m = mean[bc], r = rstd[bc];
        const float* xp = x + (size_t)bc * 65536;
        for (int i = tid; i < 37 * 37; i += 256) {
            int rr = i / 37, cc = i - rr * 37;
            int ih = ih0 + rr, iw = iw0 + cc;
            float v = 0.f;
            if ((unsigned)ih < 256u && (unsigned)iw < 256u)
                v = (xp[ih * 256 + iw] - m) * r;
            s_in[c][rr][cc] = v;
        }
    }
    __syncthreads();

    const int fg = tid >> 6;            // 0..3
    const int pg = tid & 63;
    const int prow = pg >> 2;           // 0..15
    const int pc0 = (pg & 3) * 4;       // 0,4,8,12
    const int f0 = fg * 8;

    float acc[4][8];
    #pragma unroll
    for (int p = 0; p < 4; p++)
        #pragma unroll
        for (int j = 0; j < 8; j++) acc[p][j] = 0.f;

    for (int c = 0; c < 3; c++) {
        #pragma unroll 1
        for (int kh = 0; kh < 7; kh++) {
            const float* rowp = &s_in[c][prow * 2 + kh][pc0 * 2];
            float rv[13];
            #pragma unroll
            for (int i = 0; i < 13; i++) rv[i] = rowp[i];
            #pragma unroll
            for (int kw = 0; kw < 7; kw++) {
                const float* wp = &s_w[c * 49 + kh * 7 + kw][f0];
                float4 wa = *(const float4*)wp;
                float4 wb = *(const float4*)(wp + 4);
                #pragma unroll
                for (int p = 0; p < 4; p++) {
                    float v = rv[2 * p + kw];
                    acc[p][0] += v * wa.x; acc[p][1] += v * wa.y;
                    acc[p][2] += v * wa.z; acc[p][3] += v * wa.w;
                    acc[p][4] += v * wb.x; acc[p][5] += v * wb.y;
                    acc[p][6] += v * wb.z; acc[p][7] += v * wb.w;
                }
            }
        }
    }
    int oh = oh0 + prow;
    int owb = ow0 + pc0;
    #pragma unroll
    for (int j = 0; j < 8; j++) {
        int f = f0 + j;
        float bv = bias[f];
        size_t idx = (((size_t)(b * 32 + f) * 128) + oh) * 128 + owb;
        float4 r;
        r.x = acc[0][j] + bv; r.y = acc[1][j] + bv;
        r.z = acc[2][j] + bv; r.w = acc[3][j] + bv;
        *(float4*)(out + idx) = r;
    }
}

// ---------------------------------------------------------------------------
// 3x3 conv, 32->32, stride S, pad 1, with IN + ReLU fused on input read and
// optional residual add in epilogue. Input is square IH x IH.
// Block: 256 threads, 16x16 output tile, 4px x 8f per thread, 2 cin chunks.
// ---------------------------------------------------------------------------
template<int S, int IH>
__global__ void conv3_kernel(const float* __restrict__ in,
                             const float* __restrict__ w,      // [32][32][3][3]
                             const float* __restrict__ bias,   // [32]
                             const float* __restrict__ mean,
                             const float* __restrict__ rstd,
                             const float* __restrict__ add,    // may be null
                             float* __restrict__ out)
{
    constexpr int IW = IH;
    constexpr int OH = IH / S;
    constexpr int OW = OH;
    constexpr int ITH = 16 * S + (3 - S);          // 18 (S=1) / 33 (S=2)
    constexpr int ITW = ITH;
    constexpr int ITWP = ITW + (S == 2 ? 2 : 1);   // 19 / 35
    constexpr int CHUNK = 16;

    extern __shared__ float sm[];                  // dyn smem: 16B aligned
    float* s_w = sm;                 // 32*9*32 = 9216 floats, [ (c*9+k)*32 + f ]
    float* s_in = sm + 9216;         // 9216*4 = 36864 B offset: 16B aligned

    int b = blockIdx.z;
    int oh0 = blockIdx.y * 16, ow0 = blockIdx.x * 16;
    int tid = threadIdx.x;

    for (int i = tid; i < 9216; i += 256) {
        int f = i / 288, ck = i - f * 288;
        s_w[ck * 32 + f] = w[i];
    }

    const int fg = tid >> 6;
    const int pg = tid & 63;
    const int prow = pg >> 2;
    const int pc0 = (pg & 3) * 4;
    const int f0 = fg * 8;

    float acc[4][8];
    #pragma unroll
    for (int p = 0; p < 4; p++)
        #pragma unroll
        for (int j = 0; j < 8; j++) acc[p][j] = 0.f;

    const int ih0 = oh0 * S - 1, iw0 = ow0 * S - 1;

    for (int chunk = 0; chunk < 2; chunk++) {
        __syncthreads();
        for (int i = tid; i < CHUNK * ITH * ITW; i += 256) {
            int ci = i / (ITH * ITW);
            int rem = i - ci * (ITH * ITW);
            int rr = rem / ITW, cc = rem - rr * ITW;
            int c = chunk * CHUNK + ci;
            int ih = ih0 + rr, iw = iw0 + cc;
            float v = 0.f;
            if ((unsigned)ih < (unsigned)IH && (unsigned)iw < (unsigned)IW) {
                int bc = b * 32 + c;
                float t = (in[(size_t)bc * (IH * IW) + ih * IW + iw] - mean[bc]) * rstd[bc];
                v = fmaxf(t, 0.f);
            }
            s_in[(ci * ITH + rr) * ITWP + cc] = v;
        }
        __syncthreads();

        #pragma unroll 1
        for (int ci = 0; ci < CHUNK; ci++) {
            const float* wbase = s_w + ((chunk * CHUNK + ci) * 9) * 32 + f0;
            #pragma unroll
            for (int kh = 0; kh < 3; kh++) {
                const float* rowp = s_in + (ci * ITH + prow * S + kh) * ITWP + pc0 * S;
                float rv[3 + 3 * S];
                #pragma unroll
                for (int i = 0; i < 3 + 3 * S; i++) rv[i] = rowp[i];
                #pragma unroll
                for (int kw = 0; kw < 3; kw++) {
                    const float* wp = wbase + (kh * 3 + kw) * 32;
                    float4 wa = *(const float4*)wp;
                    float4 wb = *(const float4*)(wp + 4);
                    #pragma unroll
                    for (int p = 0; p < 4; p++) {
                        float v = rv[p * S + kw];
                        acc[p][0] += v * wa.x; acc[p][1] += v * wa.y;
                        acc[p][2] += v * wa.z; acc[p][3] += v * wa.w;
                        acc[p][4] += v * wb.x; acc[p][5] += v * wb.y;
                        acc[p][6] += v * wb.z; acc[p][7] += v * wb.w;
                    }
                }
            }
        }
    }

    int oh = oh0 + prow;
    int owb = ow0 + pc0;
    #pragma unroll
    for (int j = 0; j < 8; j++) {
        int f = f0 + j;
        float bv = bias[f];
        size_t idx = (((size_t)(b * 32 + f) * OH) + oh) * OW + owb;
        float4 r;
        r.x = acc[0][j] + bv; r.y = acc[1][j] + bv;
        r.z = acc[2][j] + bv; r.w = acc[3][j] + bv;
        if (add) {
            float4 a4 = *(const float4*)(add + idx);
            r.x += a4.x; r.y += a4.y; r.z += a4.z; r.w += a4.w;
        }
        *(float4*)(out + idx) = r;
    }
}

// ---------------------------------------------------------------------------
// 1x1 stride-2 skip projection on RAW input (no norm), with bias.
// ---------------------------------------------------------------------------
template<int IH>
__global__ void skip1x1_kernel(const float* __restrict__ in,
                               const float* __restrict__ w,     // [32][32]
                               const float* __restrict__ bias,
                               float* __restrict__ out)
{
    constexpr int IW = IH;
    constexpr int OH = IH / 2;
    constexpr int OW = OH;
    __shared__ __align__(16) float s_w[32 * 32];   // [c][f]
    int b = blockIdx.z;
    int oh0 = blockIdx.y * 16, ow0 = blockIdx.x * 16;
    int tid = threadIdx.x;
    for (int i = tid; i < 1024; i += 256) {
        int f = i >> 5, c = i & 31;
        s_w[c * 32 + f] = w[i];
    }
    __syncthreads();
    int ty = tid >> 4, tx = tid & 15;
    int oh = oh0 + ty, ow = ow0 + tx;
    int ih = oh * 2, iw = ow * 2;
    float acc[32];
    #pragma unroll
    for (int f = 0; f < 32; f++) acc[f] = 0.f;
    #pragma unroll 4
    for (int c = 0; c < 32; c++) {
        float v = in[((size_t)(b * 32 + c) * IH + ih) * IW + iw];
        const float4* wp = (const float4*)(s_w + c * 32);
        #pragma unroll
        for (int j = 0; j < 8; j++) {
            float4 w4 = wp[j];
            acc[j * 4 + 0] += v * w4.x; acc[j * 4 + 1] += v * w4.y;
            acc[j * 4 + 2] += v * w4.z; acc[j * 4 + 3] += v * w4.w;
        }
    }
    #pragma unroll
    for (int f = 0; f < 32; f++)
        out[((size_t)(b * 32 + f) * OH + oh) * OW + ow] = acc[f] + bias[f];
}

// ---------------------------------------------------------------------------
// Fused attention + final linear: one block per batch sample.
// feat [64][32][16*16], text [64][256], attn_w [5][256][256], attn_b [5][256],
// final_w [512][1280], final_b [512], out [64][512]
// ---------------------------------------------------------------------------
__global__ void attn_kernel(const float* __restrict__ feat,
                            const float* __restrict__ text,
                            const float* __restrict__ attn_w,
                            const float* __restrict__ attn_b,
                            const float* __restrict__ final_w,
                            const float* __restrict__ final_b,
                            float* __restrict__ out)
{
    __shared__ __align__(16) float s_feat[32 * 256];
    __shared__ __align__(16) float s_text[256];
    __shared__ __align__(16) float s_a[5 * 256];
    __shared__ __align__(16) float s_probs[5 * 32];
    __shared__ __align__(16) float s_amap[5 * 256];

    int b = blockIdx.x;
    int tid = threadIdx.x;
    int warp = tid >> 5, lane = tid & 31;

    {
        const float4* fp = (const float4*)(feat + (size_t)b * 8192);
        float4* sp = (float4*)s_feat;
        for (int i = tid; i < 2048; i += 256) sp[i] = fp[i];
        s_text[tid] = text[b * 256 + tid];
    }
    __syncthreads();

    // gates a[h][o] = sigmoid(text . attn_w[h][o] + attn_b[h][o])
    const float4* st4 = (const float4*)s_text;
    for (int row = warp; row < 1280; row += 8) {
        const float4* wr = (const float4*)(attn_w + (size_t)row * 256);
        float s = 0.f;
        #pragma unroll
        for (int t4 = lane; t4 < 64; t4 += 32) {
            float4 wv = wr[t4];
            float4 tv = st4[t4];
            s += wv.x * tv.x + wv.y * tv.y + wv.z * tv.z + wv.w * tv.w;
        }
        #pragma unroll
        for (int o = 16; o; o >>= 1) s += __shfl_down_sync(0xffffffffu, s, o);
        if (lane == 0) {
            float v = s + attn_b[row];
            s_a[row] = 1.f / (1.f + expf(-v));
        }
    }
    __syncthreads();

    // scores[h][c] = sum_ij a[h][ij] * feat[c][ij]
    for (int row = warp; row < 160; row += 8) {
        int h = row >> 5, c = row & 31;
        float s = 0.f;
        for (int ij = lane; ij < 256; ij += 32)
            s += s_a[h * 256 + ij] * s_feat[c * 256 + ij];
        #pragma unroll
        for (int o = 16; o; o >>= 1) s += __shfl_down_sync(0xffffffffu, s, o);
        if (lane == 0) s_probs[row] = s;
    }
    __syncthreads();

    // softmax over c per head (32 lanes = 32 channels)
    if (warp < 5) {
        float v = s_probs[warp * 32 + lane];
        float mx = v;
        #pragma unroll
        for (int o = 16; o; o >>= 1) mx = fmaxf(mx, __shfl_xor_sync(0xffffffffu, mx, o));
        float e = expf(v - mx);
        float sum = e;
        #pragma unroll
        for (int o = 16; o; o >>= 1) sum += __shfl_xor_sync(0xffffffffu, sum, o);
        s_probs[warp * 32 + lane] = e / sum;
    }
    __syncthreads();

    // amaps[h][ij] = sum_c probs[h][c] * feat[c][ij]
    for (int i = tid; i < 1280; i += 256) {
        int h = i >> 8, ij = i & 255;
        float s = 0.f;
        #pragma unroll
        for (int c = 0; c < 32; c++)
            s += s_probs[h * 32 + c] * s_feat[c * 256 + ij];
        s_amap[i] = s;
    }
    __syncthreads();

    // out[e] = final_b[e] + amap . final_w[e]
    const float4* am4 = (const float4*)s_amap;
    for (int row = warp; row < 512; row += 8) {
        const float4* wr = (const float4*)(final_w + (size_t)row * 1280);
        float s = 0.f;
        #pragma unroll
        for (int k4 = lane; k4 < 320; k4 += 32) {
            float4 wv = wr[k4];
            float4 av = am4[k4];
            s += wv.x * av.x + wv.y * av.y + wv.z * av.z + wv.w * av.w;
        }
        #pragma unroll
        for (int o = 16; o; o >>= 1) s += __shfl_down_sync(0xffffffffu, s, o);
        if (lane == 0) out[b * 512 + row] = s + final_b[row];
    }
}

// ---------------------------------------------------------------------------
// Host launch
// ---------------------------------------------------------------------------
extern "C" void kernel_launch(void* const* d_in, const int* in_sizes, int n_in,
                              void* d_out, int out_size)
{
    (void)in_sizes; (void)n_in; (void)out_size;
    const float* x       = (const float*)d_in[0];
    const float* text    = (const float*)d_in[1];
    const float* conv1_w = (const float*)d_in[2];
    const float* conv1_b = (const float*)d_in[3];
    const float* rbs_w1  = (const float*)d_in[4];
    const float* rbs_b1  = (const float*)d_in[5];
    const float* rbs_w2  = (const float*)d_in[6];
    const float* rbs_b2  = (const float*)d_in[7];
    const float* rbs_ws  = (const float*)d_in[8];
    const float* rbs_bs  = (const float*)d_in[9];
    const float* rb_w1   = (const float*)d_in[10];
    const float* rb_b1   = (const float*)d_in[11];
    const float* rb_w2   = (const float*)d_in[12];
    const float* rb_b2   = (const float*)d_in[13];
    const float* attn_w  = (const float*)d_in[14];
    const float* attn_b  = (const float*)d_in[15];
    const float* final_w = (const float*)d_in[16];
    const float* final_b = (const float*)d_in[17];
    float* out = (float*)d_out;

    float *f128, *bufA, *bufB, *bufC, *bufD, *mean, *rstd;
    cudaGetSymbolAddress((void**)&f128, g_f128);
    cudaGetSymbolAddress((void**)&bufA, g_bufA);
    cudaGetSymbolAddress((void**)&bufB, g_bufB);
    cudaGetSymbolAddress((void**)&bufC, g_bufC);
    cudaGetSymbolAddress((void**)&bufD, g_bufD);
    cudaGetSymbolAddress((void**)&mean, g_mean);
    cudaGetSymbolAddress((void**)&rstd, g_rstd);

    const int SM1 = (9216 + 16 * 18 * 19) * 4;   // 58752 B
    const int SM2 = (9216 + 16 * 33 * 35) * 4;   // 110784 B
    cudaFuncSetAttribute(conv3_kernel<2, 128>, cudaFuncAttributeMaxDynamicSharedMemorySize, SM2);
    cudaFuncSetAttribute(conv3_kernel<2, 64>,  cudaFuncAttributeMaxDynamicSharedMemorySize, SM2);
    cudaFuncSetAttribute(conv3_kernel<2, 32>,  cudaFuncAttributeMaxDynamicSharedMemorySize, SM2);
    cudaFuncSetAttribute(conv3_kernel<1, 64>,  cudaFuncAttributeMaxDynamicSharedMemorySize, SM1);
    cudaFuncSetAttribute(conv3_kernel<1, 32>,  cudaFuncAttributeMaxDynamicSharedMemorySize, SM1);
    cudaFuncSetAttribute(conv3_kernel<1, 16>,  cudaFuncAttributeMaxDynamicSharedMemorySize, SM1);

    // stem: IN(x) -> conv1 (7x7 s2)
    in_stats_kernel<<<B * 3, 256>>>(x, 256 * 256, mean, rstd);
    conv1_kernel<<<dim3(8, 8, B), 256>>>(x, conv1_w, conv1_b, mean, rstd, f128);

    // strided block 0: 128 -> 64
    in_stats_kernel<<<B * F, 256>>>(f128, 128 * 128, mean, rstd);
    conv3_kernel<2, 128><<<dim3(4, 4, B), 256, SM2>>>(f128, rbs_w1, rbs_b1, mean, rstd, nullptr, bufA);
    skip1x1_kernel<128><<<dim3(4, 4, B), 256>>>(f128, rbs_ws, rbs_bs, bufB);
    in_stats_kernel<<<B * F, 256>>>(bufA, 64 * 64, mean, rstd);
    conv3_kernel<1, 64><<<dim3(4, 4, B), 256, SM1>>>(bufA, rbs_w2, rbs_b2, mean, rstd, bufB, bufC);

    // plain block 0 (64x64)
    in_stats_kernel<<<B * F, 256>>>(bufC, 64 * 64, mean, rstd);
    conv3_kernel<1, 64><<<dim3(4, 4, B), 256, SM1>>>(bufC, rb_w1, rb_b1, mean, rstd, nullptr, bufA);
    in_stats_kernel<<<B * F, 256>>>(bufA, 64 * 64, mean, rstd);
    conv3_kernel<1, 64><<<dim3(4, 4, B), 256, SM1>>>(bufA, rb_w2, rb_b2, mean, rstd, bufC, bufB);

    // strided block 1: 64 -> 32
    in_stats_kernel<<<B * F, 256>>>(bufB, 64 * 64, mean, rstd);
    conv3_kernel<2, 64><<<dim3(2, 2, B), 256, SM2>>>(bufB, rbs_w1 + 9216, rbs_b1 + 32, mean, rstd, nullptr, bufA);
    skip1x1_kernel<64><<<dim3(2, 2, B), 256>>>(bufB, rbs_ws + 1024, rbs_bs + 32, bufC);
    in_stats_kernel<<<B * F, 256>>>(bufA, 32 * 32, mean, rstd);
    conv3_kernel<1, 32><<<dim3(2, 2, B), 256, SM1>>>(bufA, rbs_w2 + 9216, rbs_b2 + 32, mean, rstd, bufC, bufD);

    // plain block 1 (32x32)
    in_stats_kernel<<<B * F, 256>>>(bufD, 32 * 32, mean, rstd);
    conv3_kernel<1, 32><<<dim3(2, 2, B), 256, SM1>>>(bufD, rb_w1 + 9216, rb_b1 + 32, mean, rstd, nullptr, bufA);
    in_stats_kernel<<<B * F, 256>>>(bufA, 32 * 32, mean, rstd);
    conv3_kernel<1, 32><<<dim3(2, 2, B), 256, SM1>>>(bufA, rb_w2 + 9216, rb_b2 + 32, mean, rstd, bufD, bufB);

    // strided block 2: 32 -> 16
    in_stats_kernel<<<B * F, 256>>>(bufB, 32 * 32, mean, rstd);
    conv3_kernel<2, 32><<<dim3(1, 1, B), 256, SM2>>>(bufB, rbs_w1 + 18432, rbs_b1 + 64, mean, rstd, nullptr, bufA);
    skip1x1_kernel<32><<<dim3(1, 1, B), 256>>>(bufB, rbs_ws + 2048, rbs_bs + 64, bufC);
    in_stats_kernel<<<B * F, 256>>>(bufA, 16 * 16, mean, rstd);
    conv3_kernel<1, 16><<<dim3(1, 1, B), 256, SM1>>>(bufA, rbs_w2 + 18432, rbs_b2 + 64, mean, rstd, bufC, bufD);

    // fused attention + final projection
    attn_kernel<<<B, 256>>>(bufD, text, attn_w, attn_b, final_w, final_b, out);
}

// round 10
// speedup vs baseline: 1.6691x; 1.6691x over previous
#include <cuda_runtime.h>
#include <cuda_bf16.h>
#include <math.h>

// ---------------------------------------------------------------------------
// Scratch buffers (device globals; no allocation allowed)
// ---------------------------------------------------------------------------
#define B 64
#define F 32

typedef unsigned long long u64;

__device__ __align__(128) float g_f128[(size_t)B * F * 128 * 128];   // 134 MB
__device__ __align__(128) float g_bufA[(size_t)B * F * 64 * 64];     // 33.5 MB each
__device__ __align__(128) float g_bufB[(size_t)B * F * 64 * 64];
__device__ __align__(128) float g_bufC[(size_t)B * F * 64 * 64];
__device__ __align__(128) float g_bufD[(size_t)B * F * 64 * 64];
__device__ float g_mean[B * F];
__device__ float g_rstd[B * F];

// ---------------------------------------------------------------------------
// Packed f32x2 helpers (Blackwell FFMA2 — only reachable via PTX)
// ---------------------------------------------------------------------------
__device__ __forceinline__ u64 pack2(float v) {
    u64 r;
    asm("mov.b64 %0, {%1, %1};" : "=l"(r) : "f"(v));
    return r;
}
__device__ __forceinline__ void fma2(u64& acc, u64 a, u64 b) {
    asm("fma.rn.f32x2 %0, %1, %2, %0;" : "+l"(acc) : "l"(a), "l"(b));
}
__device__ __forceinline__ float2 unpack2(u64 v) {
    float2 r;
    asm("mov.b64 {%0, %1}, %2;" : "=f"(r.x), "=f"(r.y) : "l"(v));
    return r;
}

// ---------------------------------------------------------------------------
// Instance-norm statistics: one block per (b,c), reduces HW elements
// ---------------------------------------------------------------------------
__global__ void in_stats_kernel(const float* __restrict__ in, int HW,
                                float* __restrict__ mean, float* __restrict__ rstd)
{
    int bc = blockIdx.x;
    const float4* p = (const float4*)(in + (size_t)bc * HW);
    int n4 = HW >> 2;
    float s1 = 0.f, s2 = 0.f;
    for (int i = threadIdx.x; i < n4; i += blockDim.x) {
        float4 v = p[i];
        s1 += v.x + v.y + v.z + v.w;
        s2 += v.x * v.x + v.y * v.y + v.z * v.z + v.w * v.w;
    }
    __shared__ float sh1[32], sh2[32];
    #pragma unroll
    for (int o = 16; o; o >>= 1) {
        s1 += __shfl_down_sync(0xffffffffu, s1, o);
        s2 += __shfl_down_sync(0xffffffffu, s2, o);
    }
    int lane = threadIdx.x & 31, w = threadIdx.x >> 5;
    if (lane == 0) { sh1[w] = s1; sh2[w] = s2; }
    __syncthreads();
    if (w == 0) {
        int nw = blockDim.x >> 5;
        s1 = lane < nw ? sh1[lane] : 0.f;
        s2 = lane < nw ? sh2[lane] : 0.f;
        #pragma unroll
        for (int o = 16; o; o >>= 1) {
            s1 += __shfl_down_sync(0xffffffffu, s1, o);
            s2 += __shfl_down_sync(0xffffffffu, s2, o);
        }
        if (lane == 0) {
            float m = s1 / (float)HW;
            float var = s2 / (float)HW - m * m;
            mean[bc] = m;
            rstd[bc] = rsqrtf(var + 1e-5f);
        }
    }
}

// ---------------------------------------------------------------------------
// conv1: 7x7 stride 2 pad 3, Cin=3 (IN applied on the fly, NO relu), Cout=32
// Input [64,3,256,256] -> output [64,32,128,128]
// 256 threads, 16x16 output tile, 4px x 8f per thread (packed channel pairs).
// ---------------------------------------------------------------------------
__global__ void conv1_kernel(const float* __restrict__ x,
                             const float* __restrict__ w,      // [32][3][7][7]
                             const float* __restrict__ bias,   // [32]
                             const float* __restrict__ mean,
                             const float* __restrict__ rstd,
                             float* __restrict__ out)
{
    __shared__ __align__(16) float s_w[147][32];   // [c*49+k][f]
    __shared__ __align__(16) float s_in[3][37][38];
    int b = blockIdx.z;
    int oh0 = blockIdx.y * 16, ow0 = blockIdx.x * 16;
    int tid = threadIdx.x;

    for (int i = tid; i < 32 * 147; i += 256) {
        int f = i / 147, ck = i - f * 147;
        s_w[ck][f] = w[i];
    }
    int ih0 = oh0 * 2 - 3, iw0 = ow0 * 2 - 3;
    for (int c = 0; c < 3; c++) {
        int bc = b * 3 + c;
        float m = mean[bc], r = rstd[bc];
        const float* xp = x + (size_t)bc * 65536;
        for (int i = tid; i < 37 * 37; i += 256) {
            int rr = i / 37, cc = i - rr * 37;
            int ih = ih0 + rr, iw = iw0 + cc;
            float v = 0.f;
            if ((unsigned)ih < 256u && (unsigned)iw < 256u)
                v = (xp[ih * 256 + iw] - m) * r;
            s_in[c][rr][cc] = v;
        }
    }
    __syncthreads();

    const int fg = tid >> 6;            // 0..3
    const int pg = tid & 63;
    const int prow = pg >> 2;           // 0..15
    const int pc0 = (pg & 3) * 4;       // 0,4,8,12
    const int f0 = fg * 8;

    u64 acc2[4][4];
    #pragma unroll
    for (int p = 0; p < 4; p++)
        #pragma unroll
        for (int q = 0; q < 4; q++) acc2[p][q] = 0ull;

    for (int c = 0; c < 3; c++) {
        #pragma unroll 1
        for (int kh = 0; kh < 7; kh++) {
            const float* rowp = &s_in[c][prow * 2 + kh][pc0 * 2];
            u64 rv2[13];
            #pragma unroll
            for (int i = 0; i < 13; i++) rv2[i] = pack2(rowp[i]);
            #pragma unroll
            for (int kw = 0; kw < 7; kw++) {
                const u64* wp = (const u64*)&s_w[c * 49 + kh * 7 + kw][f0];
                u64 w0 = wp[0], w1 = wp[1], w2 = wp[2], w3 = wp[3];
                #pragma unroll
                for (int p = 0; p < 4; p++) {
                    u64 vv = rv2[2 * p + kw];
                    fma2(acc2[p][0], vv, w0);
                    fma2(acc2[p][1], vv, w1);
                    fma2(acc2[p][2], vv, w2);
                    fma2(acc2[p][3], vv, w3);
                }
            }
        }
    }
    int oh = oh0 + prow;
    int owb = ow0 + pc0;
    #pragma unroll
    for (int q = 0; q < 4; q++) {
        float2 u0 = unpack2(acc2[0][q]), u1 = unpack2(acc2[1][q]);
        float2 u2 = unpack2(acc2[2][q]), u3 = unpack2(acc2[3][q]);
        int f = f0 + 2 * q;
        float bv0 = bias[f], bv1 = bias[f + 1];
        size_t idx0 = (((size_t)(b * 32 + f) * 128) + oh) * 128 + owb;
        size_t idx1 = idx0 + (size_t)128 * 128;
        float4 r0 = { u0.x + bv0, u1.x + bv0, u2.x + bv0, u3.x + bv0 };
        float4 r1 = { u0.y + bv1, u1.y + bv1, u2.y + bv1, u3.y + bv1 };
        *(float4*)(out + idx0) = r0;
        *(float4*)(out + idx1) = r1;
    }
}

// ---------------------------------------------------------------------------
// 3x3 conv, 32->32, stride S, pad 1, IN+ReLU fused on input read, optional
// residual add in epilogue. 256 threads, 16x16 output tile, 4px x 8f per
// thread via packed f32x2 channel pairs. cin chunked by 8 (occupancy).
// ---------------------------------------------------------------------------
template<int S, int IH>
__global__ void conv3_kernel(const float* __restrict__ in,
                             const float* __restrict__ w,      // [32][32][3][3]
                             const float* __restrict__ bias,   // [32]
                             const float* __restrict__ mean,
                             const float* __restrict__ rstd,
                             const float* __restrict__ add,    // may be null
                             float* __restrict__ out)
{
    constexpr int IW = IH;
    constexpr int OH = IH / S;
    constexpr int OW = OH;
    constexpr int ITH = 16 * S + (3 - S);          // 18 (S=1) / 33 (S=2)
    constexpr int ITW = ITH;
    constexpr int ITWP = ITW + (S == 2 ? 2 : 1);   // 19 / 35
    constexpr int CHUNK = 8;
    constexpr int NCHUNK = 32 / CHUNK;
    constexpr int RVN = 3 + 3 * S;                 // 6 / 9

    extern __shared__ float sm[];                  // dyn smem: 16B aligned
    float* s_w = sm;                 // 9216 floats, [(c*9+k)*32 + f]
    float* s_in = sm + 9216;         // CHUNK*ITH*ITWP
    __shared__ float s_m[32], s_r[32];

    int b = blockIdx.z;
    int oh0 = blockIdx.y * 16, ow0 = blockIdx.x * 16;
    int tid = threadIdx.x;

    for (int i = tid; i < 9216; i += 256) {
        int f = i / 288, ck = i - f * 288;
        s_w[ck * 32 + f] = w[i];
    }
    if (tid < 32) { s_m[tid] = mean[b * 32 + tid]; s_r[tid] = rstd[b * 32 + tid]; }

    const int fg = tid >> 6;
    const int pg = tid & 63;
    const int prow = pg >> 2;
    const int pc0 = (pg & 3) * 4;
    const int f0 = fg * 8;

    u64 acc2[4][4];
    #pragma unroll
    for (int p = 0; p < 4; p++)
        #pragma unroll
        for (int q = 0; q < 4; q++) acc2[p][q] = 0ull;

    const int ih0 = oh0 * S - 1, iw0 = ow0 * S - 1;

    for (int chunk = 0; chunk < NCHUNK; chunk++) {
        __syncthreads();
        for (int i = tid; i < CHUNK * ITH * ITW; i += 256) {
            int ci = i / (ITH * ITW);
            int rem = i - ci * (ITH * ITW);
            int rr = rem / ITW, cc = rem - rr * ITW;
            int c = chunk * CHUNK + ci;
            int ih = ih0 + rr, iw = iw0 + cc;
            float v = 0.f;
            if ((unsigned)ih < (unsigned)IH && (unsigned)iw < (unsigned)IW) {
                float t = (in[(size_t)(b * 32 + c) * (IH * IW) + ih * IW + iw] - s_m[c]) * s_r[c];
                v = fmaxf(t, 0.f);
            }
            s_in[(ci * ITH + rr) * ITWP + cc] = v;
        }
        __syncthreads();

        #pragma unroll 1
        for (int ci = 0; ci < CHUNK; ci++) {
            const float* wbase = s_w + ((chunk * CHUNK + ci) * 9) * 32 + f0;
            #pragma unroll
            for (int kh = 0; kh < 3; kh++) {
                const float* rowp = s_in + (ci * ITH + prow * S + kh) * ITWP + pc0 * S;
                u64 rv2[RVN];
                #pragma unroll
                for (int i = 0; i < RVN; i++) rv2[i] = pack2(rowp[i]);
                #pragma unroll
                for (int kw = 0; kw < 3; kw++) {
                    const u64* wp = (const u64*)(wbase + (kh * 3 + kw) * 32);
                    u64 w0 = wp[0], w1 = wp[1], w2 = wp[2], w3 = wp[3];
                    #pragma unroll
                    for (int p = 0; p < 4; p++) {
                        u64 vv = rv2[p * S + kw];
                        fma2(acc2[p][0], vv, w0);
                        fma2(acc2[p][1], vv, w1);
                        fma2(acc2[p][2], vv, w2);
                        fma2(acc2[p][3], vv, w3);
                    }
                }
            }
        }
    }

    int oh = oh0 + prow;
    int owb = ow0 + pc0;
    #pragma unroll
    for (int q = 0; q < 4; q++) {
        float2 u0 = unpack2(acc2[0][q]), u1 = unpack2(acc2[1][q]);
        float2 u2 = unpack2(acc2[2][q]), u3 = unpack2(acc2[3][q]);
        int f = f0 + 2 * q;
        float bv0 = bias[f], bv1 = bias[f + 1];
        size_t idx0 = (((size_t)(b * 32 + f) * OH) + oh) * OW + owb;
        size_t idx1 = idx0 + (size_t)OH * OW;
        float4 r0 = { u0.x + bv0, u1.x + bv0, u2.x + bv0, u3.x + bv0 };
        float4 r1 = { u0.y + bv1, u1.y + bv1, u2.y + bv1, u3.y + bv1 };
        if (add) {
            float4 a0 = *(const float4*)(add + idx0);
            float4 a1 = *(const float4*)(add + idx1);
            r0.x += a0.x; r0.y += a0.y; r0.z += a0.z; r0.w += a0.w;
            r1.x += a1.x; r1.y += a1.y; r1.z += a1.z; r1.w += a1.w;
        }
        *(float4*)(out + idx0) = r0;
        *(float4*)(out + idx1) = r1;
    }
}

// ---------------------------------------------------------------------------
// 1x1 stride-2 skip projection on RAW input (no norm), with bias. Packed.
// ---------------------------------------------------------------------------
template<int IH>
__global__ void skip1x1_kernel(const float* __restrict__ in,
                               const float* __restrict__ w,     // [32][32]
                               const float* __restrict__ bias,
                               float* __restrict__ out)
{
    constexpr int IW = IH;
    constexpr int OH = IH / 2;
    constexpr int OW = OH;
    __shared__ __align__(16) float s_w[32 * 32];   // [c][f]
    int b = blockIdx.z;
    int oh0 = blockIdx.y * 16, ow0 = blockIdx.x * 16;
    int tid = threadIdx.x;
    for (int i = tid; i < 1024; i += 256) {
        int f = i >> 5, c = i & 31;
        s_w[c * 32 + f] = w[i];
    }
    __syncthreads();
    int ty = tid >> 4, tx = tid & 15;
    int oh = oh0 + ty, ow = ow0 + tx;
    int ih = oh * 2, iw = ow * 2;
    u64 acc2[16];
    #pragma unroll
    for (int q = 0; q < 16; q++) acc2[q] = 0ull;
    #pragma unroll 4
    for (int c = 0; c < 32; c++) {
        u64 vv = pack2(in[((size_t)(b * 32 + c) * IH + ih) * IW + iw]);
        const u64* wp = (const u64*)(s_w + c * 32);
        #pragma unroll
        for (int q = 0; q < 16; q++) fma2(acc2[q], vv, wp[q]);
    }
    #pragma unroll
    for (int q = 0; q < 16; q++) {
        float2 u = unpack2(acc2[q]);
        int f = 2 * q;
        out[((size_t)(b * 32 + f) * OH + oh) * OW + ow]       = u.x + bias[f];
        out[((size_t)(b * 32 + f + 1) * OH + oh) * OW + ow]   = u.y + bias[f + 1];
    }
}

// ---------------------------------------------------------------------------
// Fused attention + final linear: one block per batch sample.
// ---------------------------------------------------------------------------
__global__ void attn_kernel(const float* __restrict__ feat,
                            const float* __restrict__ text,
                            const float* __restrict__ attn_w,
                            const float* __restrict__ attn_b,
                            const float* __restrict__ final_w,
                            const float* __restrict__ final_b,
                            float* __restrict__ out)
{
    __shared__ __align__(16) float s_feat[32 * 256];
    __shared__ __align__(16) float s_text[256];
    __shared__ __align__(16) float s_a[5 * 256];
    __shared__ __align__(16) float s_probs[5 * 32];
    __shared__ __align__(16) float s_amap[5 * 256];

    int b = blockIdx.x;
    int tid = threadIdx.x;
    int warp = tid >> 5, lane = tid & 31;

    {
        const float4* fp = (const float4*)(feat + (size_t)b * 8192);
        float4* sp = (float4*)s_feat;
        for (int i = tid; i < 2048; i += 256) sp[i] = fp[i];
        s_text[tid] = text[b * 256 + tid];
    }
    __syncthreads();

    const float4* st4 = (const float4*)s_text;
    for (int row = warp; row < 1280; row += 8) {
        const float4* wr = (const float4*)(attn_w + (size_t)row * 256);
        float s = 0.f;
        #pragma unroll
        for (int t4 = lane; t4 < 64; t4 += 32) {
            float4 wv = wr[t4];
            float4 tv = st4[t4];
            s += wv.x * tv.x + wv.y * tv.y + wv.z * tv.z + wv.w * tv.w;
        }
        #pragma unroll
        for (int o = 16; o; o >>= 1) s += __shfl_down_sync(0xffffffffu, s, o);
        if (lane == 0) {
            float v = s + attn_b[row];
            s_a[row] = 1.f / (1.f + expf(-v));
        }
    }
    __syncthreads();

    for (int row = warp; row < 160; row += 8) {
        int h = row >> 5, c = row & 31;
        float s = 0.f;
        for (int ij = lane; ij < 256; ij += 32)
            s += s_a[h * 256 + ij] * s_feat[c * 256 + ij];
        #pragma unroll
        for (int o = 16; o; o >>= 1) s += __shfl_down_sync(0xffffffffu, s, o);
        if (lane == 0) s_probs[row] = s;
    }
    __syncthreads();

    if (warp < 5) {
        float v = s_probs[warp * 32 + lane];
        float mx = v;
        #pragma unroll
        for (int o = 16; o; o >>= 1) mx = fmaxf(mx, __shfl_xor_sync(0xffffffffu, mx, o));
        float e = expf(v - mx);
        float sum = e;
        #pragma unroll
        for (int o = 16; o; o >>= 1) sum += __shfl_xor_sync(0xffffffffu, sum, o);
        s_probs[warp * 32 + lane] = e / sum;
    }
    __syncthreads();

    for (int i = tid; i < 1280; i += 256) {
        int h = i >> 8, ij = i & 255;
        float s = 0.f;
        #pragma unroll
        for (int c = 0; c < 32; c++)
            s += s_probs[h * 32 + c] * s_feat[c * 256 + ij];
        s_amap[i] = s;
    }
    __syncthreads();

    const float4* am4 = (const float4*)s_amap;
    for (int row = warp; row < 512; row += 8) {
        const float4* wr = (const float4*)(final_w + (size_t)row * 1280);
        float s = 0.f;
        #pragma unroll
        for (int k4 = lane; k4 < 320; k4 += 32) {
            float4 wv = wr[k4];
            float4 av = am4[k4];
            s += wv.x * av.x + wv.y * av.y + wv.z * av.z + wv.w * av.w;
        }
        #pragma unroll
        for (int o = 16; o; o >>= 1) s += __shfl_down_sync(0xffffffffu, s, o);
        if (lane == 0) out[b * 512 + row] = s + final_b[row];
    }
}

// ---------------------------------------------------------------------------
// Host launch
// ---------------------------------------------------------------------------
extern "C" void kernel_launch(void* const* d_in, const int* in_sizes, int n_in,
                              void* d_out, int out_size)
{
    (void)in_sizes; (void)n_in; (void)out_size;
    const float* x       = (const float*)d_in[0];
    const float* text    = (const float*)d_in[1];
    const float* conv1_w = (const float*)d_in[2];
    const float* conv1_b = (const float*)d_in[3];
    const float* rbs_w1  = (const float*)d_in[4];
    const float* rbs_b1  = (const float*)d_in[5];
    const float* rbs_w2  = (const float*)d_in[6];
    const float* rbs_b2  = (const float*)d_in[7];
    const float* rbs_ws  = (const float*)d_in[8];
    const float* rbs_bs  = (const float*)d_in[9];
    const float* rb_w1   = (const float*)d_in[10];
    const float* rb_b1   = (const float*)d_in[11];
    const float* rb_w2   = (const float*)d_in[12];
    const float* rb_b2   = (const float*)d_in[13];
    const float* attn_w  = (const float*)d_in[14];
    const float* attn_b  = (const float*)d_in[15];
    const float* final_w = (const float*)d_in[16];
    const float* final_b = (const float*)d_in[17];
    float* out = (float*)d_out;

    float *f128, *bufA, *bufB, *bufC, *bufD, *mean, *rstd;
    cudaGetSymbolAddress((void**)&f128, g_f128);
    cudaGetSymbolAddress((void**)&bufA, g_bufA);
    cudaGetSymbolAddress((void**)&bufB, g_bufB);
    cudaGetSymbolAddress((void**)&bufC, g_bufC);
    cudaGetSymbolAddress((void**)&bufD, g_bufD);
    cudaGetSymbolAddress((void**)&mean, g_mean);
    cudaGetSymbolAddress((void**)&rstd, g_rstd);

    const int SM1 = (9216 + 8 * 18 * 19) * 4;   // 47808 B -> 4 CTAs/SM
    const int SM2 = (9216 + 8 * 33 * 35) * 4;   // 73824 B -> 3 CTAs/SM
    cudaFuncSetAttribute(conv3_kernel<2, 128>, cudaFuncAttributeMaxDynamicSharedMemorySize, SM2);
    cudaFuncSetAttribute(conv3_kernel<2, 64>,  cudaFuncAttributeMaxDynamicSharedMemorySize, SM2);
    cudaFuncSetAttribute(conv3_kernel<2, 32>,  cudaFuncAttributeMaxDynamicSharedMemorySize, SM2);
    cudaFuncSetAttribute(conv3_kernel<1, 64>,  cudaFuncAttributeMaxDynamicSharedMemorySize, SM1);
    cudaFuncSetAttribute(conv3_kernel<1, 32>,  cudaFuncAttributeMaxDynamicSharedMemorySize, SM1);
    cudaFuncSetAttribute(conv3_kernel<1, 16>,  cudaFuncAttributeMaxDynamicSharedMemorySize, SM1);

    // stem: IN(x) -> conv1 (7x7 s2)
    in_stats_kernel<<<B * 3, 256>>>(x, 256 * 256, mean, rstd);
    conv1_kernel<<<dim3(8, 8, B), 256>>>(x, conv1_w, conv1_b, mean, rstd, f128);

    // strided block 0: 128 -> 64
    in_stats_kernel<<<B * F, 256>>>(f128, 128 * 128, mean, rstd);
    conv3_kernel<2, 128><<<dim3(4, 4, B), 256, SM2>>>(f128, rbs_w1, rbs_b1, mean, rstd, nullptr, bufA);
    skip1x1_kernel<128><<<dim3(4, 4, B), 256>>>(f128, rbs_ws, rbs_bs, bufB);
    in_stats_kernel<<<B * F, 256>>>(bufA, 64 * 64, mean, rstd);
    conv3_kernel<1, 64><<<dim3(4, 4, B), 256, SM1>>>(bufA, rbs_w2, rbs_b2, mean, rstd, bufB, bufC);

    // plain block 0 (64x64)
    in_stats_kernel<<<B * F, 256>>>(bufC, 64 * 64, mean, rstd);
    conv3_kernel<1, 64><<<dim3(4, 4, B), 256, SM1>>>(bufC, rb_w1, rb_b1, mean, rstd, nullptr, bufA);
    in_stats_kernel<<<B * F, 256>>>(bufA, 64 * 64, mean, rstd);
    conv3_kernel<1, 64><<<dim3(4, 4, B), 256, SM1>>>(bufA, rb_w2, rb_b2, mean, rstd, bufC, bufB);

    // strided block 1: 64 -> 32
    in_stats_kernel<<<B * F, 256>>>(bufB, 64 * 64, mean, rstd);
    conv3_kernel<2, 64><<<dim3(2, 2, B), 256, SM2>>>(bufB, rbs_w1 + 9216, rbs_b1 + 32, mean, rstd, nullptr, bufA);
    skip1x1_kernel<64><<<dim3(2, 2, B), 256>>>(bufB, rbs_ws + 1024, rbs_bs + 32, bufC);
    in_stats_kernel<<<B * F, 256>>>(bufA, 32 * 32, mean, rstd);
    conv3_kernel<1, 32><<<dim3(2, 2, B), 256, SM1>>>(bufA, rbs_w2 + 9216, rbs_b2 + 32, mean, rstd, bufC, bufD);

    // plain block 1 (32x32)
    in_stats_kernel<<<B * F, 256>>>(bufD, 32 * 32, mean, rstd);
    conv3_kernel<1, 32><<<dim3(2, 2, B), 256, SM1>>>(bufD, rb_w1 + 9216, rb_b1 + 32, mean, rstd, nullptr, bufA);
    in_stats_kernel<<<B * F, 256>>>(bufA, 32 * 32, mean, rstd);
    conv3_kernel<1, 32><<<dim3(2, 2, B), 256, SM1>>>(bufA, rb_w2 + 9216, rb_b2 + 32, mean, rstd, bufD, bufB);

    // strided block 2: 32 -> 16
    in_stats_kernel<<<B * F, 256>>>(bufB, 32 * 32, mean, rstd);
    conv3_kernel<2, 32><<<dim3(1, 1, B), 256, SM2>>>(bufB, rbs_w1 + 18432, rbs_b1 + 64, mean, rstd, nullptr, bufA);
    skip1x1_kernel<32><<<dim3(1, 1, B), 256>>>(bufB, rbs_ws + 2048, rbs_bs + 64, bufC);
    in_stats_kernel<<<B * F, 256>>>(bufA, 16 * 16, mean, rstd);
    conv3_kernel<1, 16><<<dim3(1, 1, B), 256, SM1>>>(bufA, rbs_w2 + 18432, rbs_b2 + 64, mean, rstd, bufC, bufD);

    // fused attention + final projection
    attn_kernel<<<B, 256>>>(bufD, text, attn_w, attn_b, final_w, final_b, out);
}